// round 1
// baseline (speedup 1.0000x reference)
#include <cuda_runtime.h>
#include <cuda_bf16.h>
#include <math.h>

// Problem constants
#define BB 2
#define TT 2048
#define CC 1024
#define HH 16
#define DD 64
#define CH 512
#define MM (BB*TT)   // 4096

// ---------------- scratch (static device allocs; no cudaMalloc allowed) ----
__device__ float g_h1[MM*CH];        // importance hidden
__device__ float g_xi[MM*CC];        // gated input
__device__ float g_rsnh[MM*CC];      // reasoning hidden
__device__ float g_reasoned[MM*CC];
__device__ float g_q[MM*CC];
__device__ float g_k[MM*CC];
__device__ float g_v[MM*CC];
__device__ float g_attn[MM*CC];
__device__ float g_proj[MM*CC];
__device__ float g_rmean[BB*CC];
__device__ float g_tmph[BB*CH];
__device__ float g_temp[BB*HH];

// ---------------- reductions ----------------
__device__ __forceinline__ float2 block_reduce2(float a, float b) {
    __shared__ float sa[33], sb[33];
    int lane = threadIdx.x & 31, w = threadIdx.x >> 5;
#pragma unroll
    for (int o = 16; o; o >>= 1) {
        a += __shfl_xor_sync(0xffffffffu, a, o);
        b += __shfl_xor_sync(0xffffffffu, b, o);
    }
    if (lane == 0) { sa[w] = a; sb[w] = b; }
    __syncthreads();
    if (w == 0) {
        int nw = (blockDim.x + 31) >> 5;
        a = (lane < nw) ? sa[lane] : 0.f;
        b = (lane < nw) ? sb[lane] : 0.f;
#pragma unroll
        for (int o = 16; o; o >>= 1) {
            a += __shfl_xor_sync(0xffffffffu, a, o);
            b += __shfl_xor_sync(0xffffffffu, b, o);
        }
        if (lane == 0) { sa[32] = a; sb[32] = b; }
    }
    __syncthreads();
    return make_float2(sa[32], sb[32]);
}

__device__ __forceinline__ float block_reduce1(float a) {
    __shared__ float sa[33];
    int lane = threadIdx.x & 31, w = threadIdx.x >> 5;
#pragma unroll
    for (int o = 16; o; o >>= 1) a += __shfl_xor_sync(0xffffffffu, a, o);
    if (lane == 0) sa[w] = a;
    __syncthreads();
    if (w == 0) {
        int nw = (blockDim.x + 31) >> 5;
        a = (lane < nw) ? sa[lane] : 0.f;
#pragma unroll
        for (int o = 16; o; o >>= 1) a += __shfl_xor_sync(0xffffffffu, a, o);
        if (lane == 0) sa[32] = a;
    }
    __syncthreads();
    return sa[32];
}

__device__ __forceinline__ float gelu_exact(float v) {
    return 0.5f * v * (1.f + erff(v * 0.70710678118654752f));
}

// ---------------- 128x128x8 fp32 GEMM: C = A[M,K] @ W[K,N] + bias ----------
__global__ __launch_bounds__(256) void gemm128(
        const float* __restrict__ A, const float* __restrict__ W,
        const float* __restrict__ bias, float* __restrict__ Cout,
        int M, int N, int K) {
    __shared__ float As[8][128];
    __shared__ float Bs[8][128];
    int bm = blockIdx.y * 128, bn = blockIdx.x * 128;
    int t = threadIdx.x;
    int tx = t & 15, ty = t >> 4;

    float acc[8][8];
#pragma unroll
    for (int i = 0; i < 8; i++)
#pragma unroll
        for (int j = 0; j < 8; j++) acc[i][j] = 0.f;

    int arow = t >> 1;
    int acol = (t & 1) * 4;
    const float* Aptr = A + (size_t)(bm + arow) * K + acol;
    int brow = t >> 5;
    int bcol = (t & 31) * 4;
    const float* Wptr = W + (size_t)brow * N + bn + bcol;

    for (int k0 = 0; k0 < K; k0 += 8) {
        float4 av = *(const float4*)(Aptr + k0);
        As[acol + 0][arow] = av.x;
        As[acol + 1][arow] = av.y;
        As[acol + 2][arow] = av.z;
        As[acol + 3][arow] = av.w;
        float4 bv = *(const float4*)(Wptr + (size_t)k0 * N);
        *(float4*)&Bs[brow][bcol] = bv;
        __syncthreads();
#pragma unroll
        for (int kk = 0; kk < 8; kk++) {
            float4 a0 = *(const float4*)&As[kk][ty * 4];
            float4 a1 = *(const float4*)&As[kk][64 + ty * 4];
            float4 b0 = *(const float4*)&Bs[kk][tx * 4];
            float4 b1 = *(const float4*)&Bs[kk][64 + tx * 4];
            float ar[8] = {a0.x, a0.y, a0.z, a0.w, a1.x, a1.y, a1.z, a1.w};
            float br[8] = {b0.x, b0.y, b0.z, b0.w, b1.x, b1.y, b1.z, b1.w};
#pragma unroll
            for (int i = 0; i < 8; i++)
#pragma unroll
                for (int j = 0; j < 8; j++) acc[i][j] += ar[i] * br[j];
        }
        __syncthreads();
    }

#pragma unroll
    for (int i = 0; i < 8; i++) {
        int row = bm + ((i < 4) ? (ty * 4 + i) : (64 + ty * 4 + (i - 4)));
#pragma unroll
        for (int jh = 0; jh < 2; jh++) {
            int col = bn + ((jh == 0) ? (tx * 4) : (64 + tx * 4));
            float4 o;
            o.x = acc[i][jh * 4 + 0] + bias[col + 0];
            o.y = acc[i][jh * 4 + 1] + bias[col + 1];
            o.z = acc[i][jh * 4 + 2] + bias[col + 2];
            o.w = acc[i][jh * 4 + 3] + bias[col + 3];
            *(float4*)&Cout[(size_t)row * N + col] = o;
        }
    }
}

// ---------------- LayerNorm (+ optional exact GELU), in place, per row -----
__global__ void ln_act(float* __restrict__ buf, const float* __restrict__ g,
                       const float* __restrict__ beta, int N, int do_gelu) {
    int row = blockIdx.x;
    float* p = buf + (size_t)row * N;
    float s = 0.f, ss = 0.f;
    for (int c = threadIdx.x; c < N; c += blockDim.x) {
        float v = p[c];
        s += v; ss += v * v;
    }
    float2 r = block_reduce2(s, ss);
    float mean = r.x / N;
    float var = r.y / N - mean * mean;
    float inv = rsqrtf(var + 1e-5f);
    for (int c = threadIdx.x; c < N; c += blockDim.x) {
        float v = (p[c] - mean) * inv * g[c] + beta[c];
        if (do_gelu) v = gelu_exact(v);
        p[c] = v;
    }
}

// ---------------- importance scalar + xi = x * importance ------------------
__global__ void importance_xi(const float* __restrict__ h1,
                              const float* __restrict__ w2,
                              const float* __restrict__ b2,
                              const float* __restrict__ x,
                              float* __restrict__ xi) {
    int row = blockIdx.x;
    const float* hp = h1 + (size_t)row * CH;
    float s = 0.f;
    for (int c = threadIdx.x; c < CH; c += blockDim.x) s += hp[c] * w2[c];
    float tot = block_reduce1(s);
    float v = tot + b2[0];
    float sg = 1.f / (1.f + expf(-v));
    float im = fmaxf(sg, 1e-6f);
    const float* xp = x + (size_t)row * CC;
    float* xop = xi + (size_t)row * CC;
    for (int c = threadIdx.x; c < CC; c += blockDim.x) xop[c] = xp[c] * im;
}

// ---------------- mean over T: reasoned[B,T,C] -> [B,C] --------------------
__global__ void mean_t(const float* __restrict__ r, float* __restrict__ out) {
    int b = blockIdx.y;
    int c = blockIdx.x * 256 + threadIdx.x;
    float s = 0.f;
    for (int t = 0; t < TT; t++) s += r[((size_t)b * TT + t) * CC + c];
    out[b * CC + c] = s * (1.f / TT);
}

// ---------------- tiny GEMM: one block per output element ------------------
__global__ void small_gemm(const float* __restrict__ A, const float* __restrict__ W,
                           const float* __restrict__ bias, float* __restrict__ out,
                           int K, int N) {
    int n = blockIdx.x, m = blockIdx.y;
    float s = 0.f;
    for (int k = threadIdx.x; k < K; k += blockDim.x)
        s += A[(size_t)m * K + k] * W[(size_t)k * N + n];
    float tot = block_reduce1(s);
    if (threadIdx.x == 0) out[m * N + n] = tot + bias[n];
}

__global__ void softplus_k(float* t, int n) {
    int i = threadIdx.x;
    if (i < n) {
        float x = t[i];
        float sp = (x > 20.f) ? x : log1pf(expf(x));
        t[i] = sp + 0.5f;
    }
}

// ---------------- flash attention, fp32 ------------------------------------
// grid (T/32, H, B), block 256 = 8 warps; each warp owns 4 query rows.
__global__ __launch_bounds__(256) void attn_kernel(
        const float* __restrict__ Q, const float* __restrict__ Kt,
        const float* __restrict__ V, const int* __restrict__ mask,
        const float* __restrict__ temp, float* __restrict__ Out) {
    __shared__ float Qs[32][64];
    __shared__ float Ks[32][64];   // rotation-swizzled columns
    __shared__ float Vs[32][64];
    __shared__ float Ps[8][4][32];

    int b = blockIdx.z, h = blockIdx.y;
    int q0 = blockIdx.x * 32;
    int t = threadIdx.x, lane = t & 31, w = t >> 5;
    const size_t base = ((size_t)b * TT) * CC + h * DD;

    // load Q tile (32x64)
#pragma unroll
    for (int i = 0; i < 2; i++) {
        int e = t + i * 256;
        int row = e >> 4, c4 = e & 15;
        *(float4*)&Qs[row][c4 * 4] =
            *(const float4*)&Q[base + (size_t)(q0 + row) * CC + c4 * 4];
    }
    float tmpv = temp[b * HH + h];
    const float scale = 0.125f;  // 1/sqrt(64)

    float m[4], l[4], o0[4], o1[4];
#pragma unroll
    for (int r = 0; r < 4; r++) { m[r] = -INFINITY; l[r] = 0.f; o0[r] = 0.f; o1[r] = 0.f; }

    for (int k0 = 0; k0 < TT; k0 += 32) {
        // load K (swizzled) and V tiles
#pragma unroll
        for (int i = 0; i < 2; i++) {
            int e = t + i * 256;
            int row = e >> 4, c4 = e & 15;
            int pc4 = (c4 + row) & 15;
            *(float4*)&Ks[row][pc4 * 4] =
                *(const float4*)&Kt[base + (size_t)(k0 + row) * CC + c4 * 4];
            *(float4*)&Vs[row][c4 * 4] =
                *(const float4*)&V[base + (size_t)(k0 + row) * CC + c4 * 4];
        }
        __syncthreads();

        // scores: lane j handles key k0+j for rows w*4..w*4+3
        float s[4] = {0.f, 0.f, 0.f, 0.f};
#pragma unroll
        for (int d4 = 0; d4 < 16; d4++) {
            float4 kv = *(const float4*)&Ks[lane][((d4 + lane) & 15) * 4];
#pragma unroll
            for (int r = 0; r < 4; r++) {
                float4 qv = *(const float4*)&Qs[w * 4 + r][d4 * 4];
                s[r] += qv.x * kv.x + qv.y * kv.y + qv.z * kv.z + qv.w * kv.w;
            }
        }

        int kj = k0 + lane;
#pragma unroll
        for (int r = 0; r < 4; r++) {
            int qrow = q0 + w * 4 + r;
            float sv = s[r] * scale * tmpv;
            if (mask[((size_t)b * TT + qrow) * TT + kj] == 0) sv = -INFINITY;
            // warp max
            float mx = sv;
#pragma unroll
            for (int o = 16; o; o >>= 1) mx = fmaxf(mx, __shfl_xor_sync(0xffffffffu, mx, o));
            float mnew = fmaxf(m[r], mx);
            float alpha, p;
            if (mnew == -INFINITY) { alpha = 1.f; p = 0.f; }
            else {
                alpha = __expf(m[r] - mnew);
                p = (sv == -INFINITY) ? 0.f : __expf(sv - mnew);
            }
            m[r] = mnew;
            float ps = p;
#pragma unroll
            for (int o = 16; o; o >>= 1) ps += __shfl_xor_sync(0xffffffffu, ps, o);
            l[r] = l[r] * alpha + ps;
            o0[r] *= alpha; o1[r] *= alpha;
            Ps[w][r][lane] = p;
        }
        __syncwarp();

        // o += P @ V
#pragma unroll 4
        for (int j = 0; j < 32; j++) {
            float vlo = Vs[j][lane];
            float vhi = Vs[j][lane + 32];
#pragma unroll
            for (int r = 0; r < 4; r++) {
                float pj = Ps[w][r][j];
                o0[r] += pj * vlo;
                o1[r] += pj * vhi;
            }
        }
        __syncthreads();
    }

#pragma unroll
    for (int r = 0; r < 4; r++) {
        float inv = 1.f / l[r];
        int qrow = q0 + w * 4 + r;
        Out[base + (size_t)qrow * CC + lane] = o0[r] * inv;
        Out[base + (size_t)qrow * CC + lane + 32] = o1[r] * inv;
    }
}

// ---------------- final residual + LayerNorm -------------------------------
__global__ void final_ln(const float* __restrict__ x, const float* __restrict__ pr,
                         const float* __restrict__ g, const float* __restrict__ be,
                         float* __restrict__ out) {
    int row = blockIdx.x;
    const float* xp = x + (size_t)row * CC;
    const float* pp = pr + (size_t)row * CC;
    float vals[4];
    float s = 0.f, ss = 0.f;
#pragma unroll
    for (int i = 0; i < 4; i++) {
        int c = threadIdx.x + i * 256;
        float v = xp[c] + pp[c];
        vals[i] = v;
        s += v; ss += v * v;
    }
    float2 r = block_reduce2(s, ss);
    float mean = r.x / CC;
    float var = r.y / CC - mean * mean;
    float inv = rsqrtf(var + 1e-5f);
#pragma unroll
    for (int i = 0; i < 4; i++) {
        int c = threadIdx.x + i * 256;
        out[(size_t)row * CC + c] = (vals[i] - mean) * inv * g[c] + be[c];
    }
}

// ---------------- host orchestration ---------------------------------------
extern "C" void kernel_launch(void* const* d_in, const int* in_sizes, int n_in,
                              void* d_out, int out_size) {
    const float* x        = (const float*)d_in[0];
    const int*   amask    = (const int*)d_in[1];
    const float* imp_w1   = (const float*)d_in[2];
    const float* imp_b1   = (const float*)d_in[3];
    const float* imp_g    = (const float*)d_in[4];
    const float* imp_beta = (const float*)d_in[5];
    const float* imp_w2   = (const float*)d_in[6];
    const float* imp_b2   = (const float*)d_in[7];
    const float* rsn_w1   = (const float*)d_in[8];
    const float* rsn_b1   = (const float*)d_in[9];
    const float* rsn_g    = (const float*)d_in[10];
    const float* rsn_beta = (const float*)d_in[11];
    const float* rsn_w2   = (const float*)d_in[12];
    const float* rsn_b2   = (const float*)d_in[13];
    const float* q_w      = (const float*)d_in[14];
    const float* q_b      = (const float*)d_in[15];
    const float* k_w      = (const float*)d_in[16];
    const float* k_b      = (const float*)d_in[17];
    const float* v_w      = (const float*)d_in[18];
    const float* v_b      = (const float*)d_in[19];
    const float* o_w      = (const float*)d_in[20];
    const float* o_b      = (const float*)d_in[21];
    const float* tmp_w1   = (const float*)d_in[22];
    const float* tmp_b1   = (const float*)d_in[23];
    const float* tmp_g    = (const float*)d_in[24];
    const float* tmp_beta = (const float*)d_in[25];
    const float* tmp_w2   = (const float*)d_in[26];
    const float* tmp_b2   = (const float*)d_in[27];
    const float* norm_g   = (const float*)d_in[28];
    const float* norm_b   = (const float*)d_in[29];

    float *p_h1, *p_xi, *p_rsnh, *p_rsn, *p_q, *p_k, *p_v, *p_at, *p_pr;
    float *p_rm, *p_th, *p_tp;
    cudaGetSymbolAddress((void**)&p_h1,  g_h1);
    cudaGetSymbolAddress((void**)&p_xi,  g_xi);
    cudaGetSymbolAddress((void**)&p_rsnh, g_rsnh);
    cudaGetSymbolAddress((void**)&p_rsn, g_reasoned);
    cudaGetSymbolAddress((void**)&p_q,   g_q);
    cudaGetSymbolAddress((void**)&p_k,   g_k);
    cudaGetSymbolAddress((void**)&p_v,   g_v);
    cudaGetSymbolAddress((void**)&p_at,  g_attn);
    cudaGetSymbolAddress((void**)&p_pr,  g_proj);
    cudaGetSymbolAddress((void**)&p_rm,  g_rmean);
    cudaGetSymbolAddress((void**)&p_th,  g_tmph);
    cudaGetSymbolAddress((void**)&p_tp,  g_temp);

    // importance net
    gemm128<<<dim3(CH / 128, MM / 128), 256>>>(x, imp_w1, imp_b1, p_h1, MM, CH, CC);
    ln_act<<<MM, 256>>>(p_h1, imp_g, imp_beta, CH, 1);
    importance_xi<<<MM, 256>>>(p_h1, imp_w2, imp_b2, x, p_xi);

    // reasoning net
    gemm128<<<dim3(CC / 128, MM / 128), 256>>>(p_xi, rsn_w1, rsn_b1, p_rsnh, MM, CC, CC);
    ln_act<<<MM, 256>>>(p_rsnh, rsn_g, rsn_beta, CC, 1);
    gemm128<<<dim3(CC / 128, MM / 128), 256>>>(p_rsnh, rsn_w2, rsn_b2, p_rsn, MM, CC, CC);

    // projections
    gemm128<<<dim3(CC / 128, MM / 128), 256>>>(p_rsn, q_w, q_b, p_q, MM, CC, CC);
    gemm128<<<dim3(CC / 128, MM / 128), 256>>>(p_xi, k_w, k_b, p_k, MM, CC, CC);
    gemm128<<<dim3(CC / 128, MM / 128), 256>>>(x, v_w, v_b, p_v, MM, CC, CC);

    // temperature net
    mean_t<<<dim3(CC / 256, BB), 256>>>(p_rsn, p_rm);
    small_gemm<<<dim3(CH, BB), 128>>>(p_rm, tmp_w1, tmp_b1, p_th, CC, CH);
    ln_act<<<BB, 256>>>(p_th, tmp_g, tmp_beta, CH, 1);
    small_gemm<<<dim3(HH, BB), 128>>>(p_th, tmp_w2, tmp_b2, p_tp, CH, HH);
    softplus_k<<<1, 32>>>(p_tp, BB * HH);

    // attention
    attn_kernel<<<dim3(TT / 32, HH, BB), 256>>>(p_q, p_k, p_v, amask, p_tp, p_at);

    // output projection + residual LN
    gemm128<<<dim3(CC / 128, MM / 128), 256>>>(p_at, o_w, o_b, p_pr, MM, CC, CC);
    final_ln<<<MM, 256>>>(x, p_pr, norm_g, norm_b, (float*)d_out);
}